// round 14
// baseline (speedup 1.0000x reference)
#include <cuda_runtime.h>

#define H_IN   200
#define W_IN   320
#define C_IN   64
#define H_OUT  48
#define W_OUT  320

#define SRC_CH_STRIDE (H_IN * W_IN)    // 64000 floats
#define DST_CH_STRIDE (H_OUT * W_OUT)  // 15360 floats

#define QUADS     (W_OUT / 4)          // 80 column-quads per row
#define NTHREADS  256
#define NUNITS    (H_OUT * QUADS)      // 3840 float4 units per (box,channel) tile
#define NITERS    (NUNITS / NTHREADS)  // 15
#define CPAIR     2                    // channels per block, written back-to-back

__global__ void __launch_bounds__(NTHREADS)
roi_crop_kernel(const float* __restrict__ x,
                const int*   __restrict__ bboxes,
                const int*   __restrict__ box_img,
                float*       __restrict__ out)
{
    const int c0 = blockIdx.x * CPAIR;  // first channel of pair
    const int b  = blockIdx.y;          // box 0..255
    const int t  = threadIdx.x;         // 0..255

    __shared__ int4 s_colq[QUADS];   // 4 source cols per output quad
    __shared__ int  s_row[H_OUT];    // source row per output row

    // bbox decode (uniform per block)
    int x0 = __ldg(&bboxes[b * 4 + 0]);
    int y0 = __ldg(&bboxes[b * 4 + 1]);
    int x1 = __ldg(&bboxes[b * 4 + 2]);
    int y1 = __ldg(&bboxes[b * 4 + 3]);
    x0 = min(max(x0, 0), W_IN - 1);
    y0 = min(max(y0, 0), H_IN - 1);
    x1 = min(max(x1, 0), W_IN - 1);
    y1 = min(max(y1, 0), H_IN - 1);
    x1 = max(x1, x0);
    y1 = max(y1, y0);
    const int h = y1 - y0 + 1;
    const int w = x1 - x0 + 1;

    if (t < QUADS) {                         // 80 threads fill column quads
        const int j0 = t * 4;
        int4 cq;
        cq.x = x0 + ((j0 + 0) * w) / W_OUT;  // const-divisor -> mul/shift
        cq.y = x0 + ((j0 + 1) * w) / W_OUT;
        cq.z = x0 + ((j0 + 2) * w) / W_OUT;
        cq.w = x0 + ((j0 + 3) * w) / W_OUT;
        s_colq[t] = cq;
    }
    if (t >= 128 && t < 128 + H_OUT)         // 48 threads fill row map
        s_row[t - 128] = y0 + ((t - 128) * h) / H_OUT;
    __syncthreads();

    const int img = __ldg(&box_img[b]);
    const float* __restrict__ src0 =
        x + (size_t)img * (C_IN * SRC_CH_STRIDE) + (size_t)c0 * SRC_CH_STRIDE;
    float4* __restrict__ dst0 =
        (float4*)(out + ((size_t)b * C_IN + c0) * DST_CH_STRIDE);

    // Two consecutive channel tiles written back-to-back in time:
    // 2 x 61440 B = 122,880 B of block-sequential plain STG.128 stream.
    // Inner loop identical to the 168.4us kernel (depth-2 pipelined gathers).
    for (int cc = 0; cc < CPAIR; cc++) {
        const float* __restrict__ src = src0 + cc * SRC_CH_STRIDE;
        float4* __restrict__ dst = dst0 + cc * (DST_CH_STRIDE / 4);

        int u = t;
        int i = u / QUADS;
        int q = u - i * QUADS;
        int4 cq = s_colq[q];
        const float* s = src + s_row[i] * W_IN;
        float4 v;
        v.x = __ldg(s + cq.x);
        v.y = __ldg(s + cq.y);
        v.z = __ldg(s + cq.z);
        v.w = __ldg(s + cq.w);

        #pragma unroll
        for (int m = 0; m < NITERS - 1; m++) {
            const int un = u + NTHREADS;
            const int in = un / QUADS;
            const int qn = un - in * QUADS;
            const int4 cqn = s_colq[qn];
            const float* sn = src + s_row[in] * W_IN;
            float4 vn;
            vn.x = __ldg(sn + cqn.x);
            vn.y = __ldg(sn + cqn.y);
            vn.z = __ldg(sn + cqn.z);
            vn.w = __ldg(sn + cqn.w);

            dst[u] = v;      // store m while m+1's loads are in flight
            v = vn;
            u = un;
        }
        dst[u] = v;
    }
}

extern "C" void kernel_launch(void* const* d_in, const int* in_sizes, int n_in,
                              void* d_out, int out_size)
{
    const float* x       = (const float*)d_in[0];
    const int*   bboxes  = (const int*)d_in[1];
    const int*   box_img = (const int*)d_in[2];
    float*       out     = (float*)d_out;

    dim3 grid(C_IN / CPAIR, 256);         // (32 channel-pairs, 256 boxes)
    roi_crop_kernel<<<grid, NTHREADS>>>(x, bboxes, box_img, out);
}

// round 17
// speedup vs baseline: 1.0721x; 1.0721x over previous
#include <cuda_runtime.h>

#define H_IN   200
#define W_IN   320
#define C_IN   64
#define H_OUT  48
#define W_OUT  320

#define SRC_CH_STRIDE (H_IN * W_IN)    // 64000 floats
#define DST_CH_STRIDE (H_OUT * W_OUT)  // 15360 floats

#define QUADS     (W_OUT / 4)          // 80 column-quads per row
#define NTHREADS  256
#define NUNITS    (H_OUT * QUADS)      // 3840 float4 units per (box,channel) tile
#define NITERS    (NUNITS / NTHREADS)  // 15

__global__ void __launch_bounds__(NTHREADS)
roi_crop_kernel(const float* __restrict__ x,
                const int*   __restrict__ bboxes,
                const int*   __restrict__ box_img,
                float*       __restrict__ out)
{
    const int c = blockIdx.x;    // channel 0..63
    const int b = blockIdx.y;    // box 0..255
    const int t = threadIdx.x;   // 0..255

    __shared__ int4 s_colq[QUADS];   // 4 source cols per output quad
    __shared__ int  s_row[H_OUT];    // source row per output row

    // bbox decode (uniform per block)
    int x0 = __ldg(&bboxes[b * 4 + 0]);
    int y0 = __ldg(&bboxes[b * 4 + 1]);
    int x1 = __ldg(&bboxes[b * 4 + 2]);
    int y1 = __ldg(&bboxes[b * 4 + 3]);
    x0 = min(max(x0, 0), W_IN - 1);
    y0 = min(max(y0, 0), H_IN - 1);
    x1 = min(max(x1, 0), W_IN - 1);
    y1 = min(max(y1, 0), H_IN - 1);
    x1 = max(x1, x0);
    y1 = max(y1, y0);
    const int h = y1 - y0 + 1;
    const int w = x1 - x0 + 1;

    if (t < QUADS) {                         // 80 threads fill column quads
        const int j0 = t * 4;
        int4 cq;
        cq.x = x0 + ((j0 + 0) * w) / W_OUT;  // const-divisor -> mul/shift
        cq.y = x0 + ((j0 + 1) * w) / W_OUT;
        cq.z = x0 + ((j0 + 2) * w) / W_OUT;
        cq.w = x0 + ((j0 + 3) * w) / W_OUT;
        s_colq[t] = cq;
    }
    if (t >= 128 && t < 128 + H_OUT)         // 48 threads fill row map
        s_row[t - 128] = y0 + ((t - 128) * h) / H_OUT;
    __syncthreads();

    const int img = __ldg(&box_img[b]);
    const float* __restrict__ src =
        x + (size_t)img * (C_IN * SRC_CH_STRIDE) + (size_t)c * SRC_CH_STRIDE;
    // This block's output tile: 61440 bytes, written fully sequentially.
    float4* __restrict__ dst =
        (float4*)(out + ((size_t)b * C_IN + c) * DST_CH_STRIDE);

    // Depth-2 software pipeline (identical to the 168.4us kernel) with
    // evict-first streaming stores: output lines don't churn L2, protecting
    // the input's L2 residency.
    int u = t;
    int i = u / QUADS;
    int q = u - i * QUADS;
    int4 cq = s_colq[q];
    const float* s = src + s_row[i] * W_IN;
    float4 v;
    v.x = __ldg(s + cq.x);
    v.y = __ldg(s + cq.y);
    v.z = __ldg(s + cq.z);
    v.w = __ldg(s + cq.w);

    #pragma unroll
    for (int m = 0; m < NITERS - 1; m++) {
        const int un = u + NTHREADS;
        const int in = un / QUADS;
        const int qn = un - in * QUADS;
        const int4 cqn = s_colq[qn];
        const float* sn = src + s_row[in] * W_IN;
        float4 vn;
        vn.x = __ldg(sn + cqn.x);
        vn.y = __ldg(sn + cqn.y);
        vn.z = __ldg(sn + cqn.z);
        vn.w = __ldg(sn + cqn.w);

        __stcs(dst + u, v);  // store m (evict-first) while m+1's loads fly
        v = vn;
        u = un;
    }
    __stcs(dst + u, v);
}

extern "C" void kernel_launch(void* const* d_in, const int* in_sizes, int n_in,
                              void* d_out, int out_size)
{
    const float* x       = (const float*)d_in[0];
    const int*   bboxes  = (const int*)d_in[1];
    const int*   box_img = (const int*)d_in[2];
    float*       out     = (float*)d_out;

    dim3 grid(C_IN, 256);                 // (64 channels, 256 boxes)
    roi_crop_kernel<<<grid, NTHREADS>>>(x, bboxes, box_img, out);
}